// round 4
// baseline (speedup 1.0000x reference)
#include <cuda_runtime.h>
#include <cstdint>

// Shapes (fixed): B=4, N=50000
//  f1:[B,64,56,56] f2:[B,128,28,28] f3:[B,256,14,14] f4:[B,512,7,7]
//  out:[B,N,963] = 3 coord + 64 + 128 + 256 + 512

#define BMAX 4

// Transposed feature scratch: [b][x][y][c] (channel-contiguous per texel)
__device__ float g_t1[BMAX * 56 * 56 * 64];
__device__ float g_t2[BMAX * 28 * 28 * 128];
__device__ float g_t3[BMAX * 14 * 14 * 256];
__device__ float g_t4[BMAX * 7  * 7  * 512];

// ---------------------------------------------------------------------------
__global__ void transpose_kernel(const float* __restrict__ in,
                                 float* __restrict__ out,
                                 int C, int S, int total) {
    int idx = blockIdx.x * blockDim.x + threadIdx.x;
    if (idx >= total) return;
    int c = idx % C;
    int y = (idx / C) % S;
    int x = (idx / (C * S)) % S;
    int b = idx / (C * S * S);
    out[idx] = in[((b * C + c) * S + x) * S + y];
}

// ---------------------------------------------------------------------------
// Bilinear params for one level. Reproduces the reference exactly, including
// the all-zero-weight case when the clipped coord is an integer (floor==ceil).
__device__ __forceinline__ void level_params(float h, float w, float invsc,
                                             int S, int C, int base,
                                             float* wout, int* oout) {
    float x = fminf(h * invsc, (float)(S - 1));
    float y = fminf(w * invsc, (float)(S - 1));
    float x1f = floorf(x), x2f = ceilf(x);
    float y1f = floorf(y), y2f = ceilf(y);
    int x1 = (int)x1f, x2 = (int)x2f, y1 = (int)y1f, y2 = (int)y2f;
    float ax2 = x2f - x, ax1 = x - x1f;
    float ay2 = y2f - y, ay1 = y - y1f;
    oout[0] = base + (x1 * S + y1) * C;   // Q11
    oout[1] = base + (x2 * S + y1) * C;   // Q21
    oout[2] = base + (x1 * S + y2) * C;   // Q12
    oout[3] = base + (x2 * S + y2) * C;   // Q22
    wout[0] = ax2 * ay2;
    wout[1] = ax1 * ay2;
    wout[2] = ax2 * ay1;
    wout[3] = ax1 * ay1;
}

__device__ __forceinline__ void point_hw(const float* __restrict__ coord, int n,
                                         float& h, float& w) {
    float X = coord[3 * n + 0];
    float Y = coord[3 * n + 1];
    float Z = coord[3 * n + 2];
    float negZ = -Z;
    h = fminf(fmaxf(250.0f * (-Y) / negZ + 112.0f, 0.0f), 223.0f);
    w = fminf(fmaxf(250.0f * X / negZ + 112.0f, 0.0f), 223.0f);
}

// ---------------------------------------------------------------------------
// Kernel A: channels [0,451) = coord(3) + f1(64) + f2(128) + f3(256).
// f3 batch slice (200704 B) staged in shared memory.
// ---------------------------------------------------------------------------
#define PTS_A 256
#define F3_ELEMS (14 * 14 * 256)   // 50176 floats per batch

__global__ __launch_bounds__(256)
void gather_A(const float* __restrict__ coord,
              const float* __restrict__ t1,
              const float* __restrict__ t2,
              const float* __restrict__ t3,
              float* __restrict__ out, int N) {
    extern __shared__ float sm[];
    float* sf3 = sm;                                   // 50176 floats
    float* sw  = sm + F3_ELEMS;                        // [PTS_A][12]
    int*   so  = (int*)(sw + PTS_A * 12);              // [PTS_A][12]

    const int b   = blockIdx.y;
    const int n0  = blockIdx.x * PTS_A;
    const int tid = threadIdx.x;
    const int npts = min(PTS_A, N - n0);

    // Stage f3[b] -> smem (coalesced float4 copy)
    {
        const float4* src = (const float4*)(t3 + (size_t)b * F3_ELEMS);
        float4* dst = (float4*)sf3;
        #pragma unroll 4
        for (int i = tid; i < F3_ELEMS / 4; i += 256) dst[i] = src[i];
    }

    if (tid < npts) {
        int n = n0 + tid;
        float h, w;
        point_hw(coord, n, h, w);
        level_params(h, w, 0.25f,   56, 64,  b * 56 * 56 * 64,  &sw[tid * 12 + 0], &so[tid * 12 + 0]);
        level_params(h, w, 0.125f,  28, 128, b * 28 * 28 * 128, &sw[tid * 12 + 4], &so[tid * 12 + 4]);
        level_params(h, w, 0.0625f, 14, 256, 0,                 &sw[tid * 12 + 8], &so[tid * 12 + 8]);
    }

    // Coord channels (0..2) for this tile: straight copy, coalesced read+write.
    for (int i = tid; i < npts * 3; i += 256) {
        int p = i / 3, k = i % 3;
        out[((size_t)b * N + n0 + p) * 963 + k] = coord[3 * n0 + i];
    }
    __syncthreads();

    for (int p = 0; p < npts; p++) {
        float* o = out + ((size_t)b * N + n0 + p) * 963 + 3;
        const float* wp = &sw[p * 12];
        const int*   op = &so[p * 12];
        #pragma unroll 2
        for (int ch = tid; ch < 448; ch += 256) {
            float v;
            if (ch < 64) {
                v = wp[0] * t1[op[0] + ch] + wp[1] * t1[op[1] + ch]
                  + wp[2] * t1[op[2] + ch] + wp[3] * t1[op[3] + ch];
            } else if (ch < 192) {
                int c = ch - 64;
                v = wp[4] * t2[op[4] + c] + wp[5] * t2[op[5] + c]
                  + wp[6] * t2[op[6] + c] + wp[7] * t2[op[7] + c];
            } else {
                int c = ch - 192;
                v = wp[8]  * sf3[op[8]  + c] + wp[9]  * sf3[op[9]  + c]
                  + wp[10] * sf3[op[10] + c] + wp[11] * sf3[op[11] + c];
            }
            o[ch] = v;
        }
    }
}

// ---------------------------------------------------------------------------
// Kernel B: channels [451,963) = f4(512). f4 batch slice (100352 B) in smem.
// ---------------------------------------------------------------------------
#define PTS_B 256
#define F4_ELEMS (7 * 7 * 512)   // 25088 floats per batch

__global__ __launch_bounds__(256)
void gather_B(const float* __restrict__ coord,
              const float* __restrict__ t4,
              float* __restrict__ out, int N) {
    extern __shared__ float sm[];
    float* sf4 = sm;                          // 25088 floats
    float* sw  = sm + F4_ELEMS;               // [PTS_B][4]
    int*   so  = (int*)(sw + PTS_B * 4);      // [PTS_B][4]

    const int b   = blockIdx.y;
    const int n0  = blockIdx.x * PTS_B;
    const int tid = threadIdx.x;
    const int npts = min(PTS_B, N - n0);

    {
        const float4* src = (const float4*)(t4 + (size_t)b * F4_ELEMS);
        float4* dst = (float4*)sf4;
        #pragma unroll 4
        for (int i = tid; i < F4_ELEMS / 4; i += 256) dst[i] = src[i];
    }

    if (tid < npts) {
        int n = n0 + tid;
        float h, w;
        point_hw(coord, n, h, w);
        level_params(h, w, 0.03125f, 7, 512, 0, &sw[tid * 4], &so[tid * 4]);
    }
    __syncthreads();

    for (int p = 0; p < npts; p++) {
        float* o = out + ((size_t)b * N + n0 + p) * 963 + 451;
        const float w0 = sw[p * 4 + 0], w1 = sw[p * 4 + 1];
        const float w2 = sw[p * 4 + 2], w3 = sw[p * 4 + 3];
        const int   o0 = so[p * 4 + 0], o1 = so[p * 4 + 1];
        const int   o2 = so[p * 4 + 2], o3 = so[p * 4 + 3];
        #pragma unroll
        for (int it = 0; it < 2; it++) {
            int c = tid + it * 256;
            o[c] = w0 * sf4[o0 + c] + w1 * sf4[o1 + c]
                 + w2 * sf4[o2 + c] + w3 * sf4[o3 + c];
        }
    }
}

// ---------------------------------------------------------------------------
extern "C" void kernel_launch(void* const* d_in, const int* in_sizes, int n_in,
                              void* d_out, int out_size) {
    const float* inputs = (const float*)d_in[0];  // [B,N,3]; coord = inputs[0]
    const float* f1 = (const float*)d_in[1];
    const float* f2 = (const float*)d_in[2];
    const float* f3 = (const float*)d_in[3];
    const float* f4 = (const float*)d_in[4];
    float* out = (float*)d_out;

    const int B = in_sizes[1] / (64 * 56 * 56);
    const int N = in_sizes[0] / (3 * B);

    float* t1; float* t2; float* t3; float* t4;
    cudaGetSymbolAddress((void**)&t1, g_t1);
    cudaGetSymbolAddress((void**)&t2, g_t2);
    cudaGetSymbolAddress((void**)&t3, g_t3);
    cudaGetSymbolAddress((void**)&t4, g_t4);

    const int thr = 256;
    { int total = B * 64 * 56 * 56;  transpose_kernel<<<(total + thr - 1) / thr, thr>>>(f1, t1, 64, 56, total); }
    { int total = B * 128 * 28 * 28; transpose_kernel<<<(total + thr - 1) / thr, thr>>>(f2, t2, 128, 28, total); }
    { int total = B * 256 * 14 * 14; transpose_kernel<<<(total + thr - 1) / thr, thr>>>(f3, t3, 256, 14, total); }
    { int total = B * 512 * 7 * 7;   transpose_kernel<<<(total + thr - 1) / thr, thr>>>(f4, t4, 512, 7, total); }

    // Dynamic smem sizes
    const int smemA = F3_ELEMS * 4 + PTS_A * 12 * 4 * 2;   // 200704 + 24576 = 225280 B
    const int smemB = F4_ELEMS * 4 + PTS_B * 4 * 4 * 2;    // 100352 + 8192  = 108544 B
    cudaFuncSetAttribute(gather_A, cudaFuncAttributeMaxDynamicSharedMemorySize, smemA);
    cudaFuncSetAttribute(gather_B, cudaFuncAttributeMaxDynamicSharedMemorySize, smemB);

    dim3 gridA((N + PTS_A - 1) / PTS_A, B);
    gather_A<<<gridA, 256, smemA>>>(inputs, t1, t2, t3, out, N);

    dim3 gridB((N + PTS_B - 1) / PTS_B, B);
    gather_B<<<gridB, 256, smemB>>>(inputs, t4, out, N);
}

// round 8
// speedup vs baseline: 3.5004x; 3.5004x over previous
#include <cuda_runtime.h>
#include <cstdint>

// Shapes (fixed): B=4, N=50000
//  f1:[B,64,56,56] f2:[B,128,28,28] f3:[B,256,14,14] f4:[B,512,7,7]
//  out:[B,N,963] = 3 coord + 64 + 128 + 256 + 512

#define BMAX 4

// Transposed feature scratch: [b][x][y][c] (channel-contiguous per texel)
__device__ float g_t1[BMAX * 56 * 56 * 64];
__device__ float g_t2[BMAX * 28 * 28 * 128];
__device__ float g_t3[BMAX * 14 * 14 * 256];
__device__ float g_t4[BMAX * 7  * 7  * 512];

// ---------------------------------------------------------------------------
__global__ void transpose_kernel(const float* __restrict__ in,
                                 float* __restrict__ out,
                                 int C, int S, int total) {
    int idx = blockIdx.x * blockDim.x + threadIdx.x;
    if (idx >= total) return;
    int c = idx % C;
    int y = (idx / C) % S;
    int x = (idx / (C * S)) % S;
    int b = idx / (C * S * S);
    out[idx] = in[((b * C + c) * S + x) * S + y];
}

// ---------------------------------------------------------------------------
// Bilinear params for one level. Matches the reference exactly, including the
// all-zero-weight case when the clipped coord is an integer (floor==ceil).
__device__ __forceinline__ void level_params(float h, float w, float invsc,
                                             int S, int C, int base,
                                             float* wout, int* oout) {
    float x = fminf(h * invsc, (float)(S - 1));
    float y = fminf(w * invsc, (float)(S - 1));
    float x1f = floorf(x), x2f = ceilf(x);
    float y1f = floorf(y), y2f = ceilf(y);
    int x1 = (int)x1f, x2 = (int)x2f, y1 = (int)y1f, y2 = (int)y2f;
    float ax2 = x2f - x, ax1 = x - x1f;
    float ay2 = y2f - y, ay1 = y - y1f;
    oout[0] = base + (x1 * S + y1) * C;   // Q11
    oout[1] = base + (x2 * S + y1) * C;   // Q21
    oout[2] = base + (x1 * S + y2) * C;   // Q12
    oout[3] = base + (x2 * S + y2) * C;   // Q22
    wout[0] = ax2 * ay2;
    wout[1] = ax1 * ay2;
    wout[2] = ax2 * ay1;
    wout[3] = ax1 * ay1;
}

// ---------------------------------------------------------------------------
// One level's gather. Block = 256 threads = PT points x C4 float4-channels.
// Tiny smem -> full occupancy. Vectorized (float4) corner loads; streaming
// (evict-first) scalar stores so the 770MB write stream doesn't thrash L2.
// Batch is the slow grid index so concurrent CTAs share one batch's slice of
// this level in L1/L2.
// WRITE_COORD: the f1 kernel also emits output channels 0..2 (the raw coords).
// ---------------------------------------------------------------------------
template<int C4, int PT, int LOG_C4, bool WRITE_COORD>
__global__ __launch_bounds__(256)
void gather_level(const float* __restrict__ coord,
                  const float* __restrict__ t,
                  float* __restrict__ out,
                  int N, int S, float invsc, int ch_off) {
    __shared__ float sw[PT][4];
    __shared__ int   so[PT][4];

    const int b   = blockIdx.y;
    const int n0  = blockIdx.x * PT;
    const int tid = threadIdx.x;
    constexpr int C = C4 * 4;

    if (tid < PT) {
        int n = n0 + tid;
        if (n < N) {
            float X = coord[3 * n + 0];
            float Y = coord[3 * n + 1];
            float Z = coord[3 * n + 2];
            float negZ = -Z;
            float h = fminf(fmaxf(250.0f * (-Y) / negZ + 112.0f, 0.0f), 223.0f);
            float w = fminf(fmaxf(250.0f * X / negZ + 112.0f, 0.0f), 223.0f);
            level_params(h, w, invsc, S, C, b * S * S * C, sw[tid], so[tid]);
            if (WRITE_COORD) {
                float* oc = out + ((size_t)b * N + n) * 963;
                __stcs(oc + 0, X);
                __stcs(oc + 1, Y);
                __stcs(oc + 2, Z);
            }
        }
    }
    __syncthreads();

    const int p = tid >> LOG_C4;
    const int c = (tid & (C4 - 1)) * 4;
    const int n = n0 + p;
    if (n >= N) return;

    const float w0 = sw[p][0], w1 = sw[p][1], w2 = sw[p][2], w3 = sw[p][3];
    const float4 q0 = *(const float4*)(t + so[p][0] + c);
    const float4 q1 = *(const float4*)(t + so[p][1] + c);
    const float4 q2 = *(const float4*)(t + so[p][2] + c);
    const float4 q3 = *(const float4*)(t + so[p][3] + c);

    float* o = out + ((size_t)b * N + n) * 963 + ch_off + c;
    __stcs(o + 0, w0 * q0.x + w1 * q1.x + w2 * q2.x + w3 * q3.x);
    __stcs(o + 1, w0 * q0.y + w1 * q1.y + w2 * q2.y + w3 * q3.y);
    __stcs(o + 2, w0 * q0.z + w1 * q1.z + w2 * q2.z + w3 * q3.z);
    __stcs(o + 3, w0 * q0.w + w1 * q1.w + w2 * q2.w + w3 * q3.w);
}

// ---------------------------------------------------------------------------
extern "C" void kernel_launch(void* const* d_in, const int* in_sizes, int n_in,
                              void* d_out, int out_size) {
    const float* inputs = (const float*)d_in[0];  // [B,N,3]; coord = inputs[0]
    const float* f1 = (const float*)d_in[1];
    const float* f2 = (const float*)d_in[2];
    const float* f3 = (const float*)d_in[3];
    const float* f4 = (const float*)d_in[4];
    float* out = (float*)d_out;

    const int B = in_sizes[1] / (64 * 56 * 56);
    const int N = in_sizes[0] / (3 * B);

    float* t1; float* t2; float* t3; float* t4;
    cudaGetSymbolAddress((void**)&t1, g_t1);
    cudaGetSymbolAddress((void**)&t2, g_t2);
    cudaGetSymbolAddress((void**)&t3, g_t3);
    cudaGetSymbolAddress((void**)&t4, g_t4);

    const int thr = 256;
    { int total = B * 64 * 56 * 56;  transpose_kernel<<<(total + thr - 1) / thr, thr>>>(f1, t1, 64, 56, total); }
    { int total = B * 128 * 28 * 28; transpose_kernel<<<(total + thr - 1) / thr, thr>>>(f2, t2, 128, 28, total); }
    { int total = B * 256 * 14 * 14; transpose_kernel<<<(total + thr - 1) / thr, thr>>>(f3, t3, 256, 14, total); }
    { int total = B * 512 * 7 * 7;   transpose_kernel<<<(total + thr - 1) / thr, thr>>>(f4, t4, 512, 7, total); }

    {   // f4: C=512, C4=128, PT=2
        dim3 grid((N + 2 - 1) / 2, B);
        gather_level<128, 2, 7, false><<<grid, 256>>>(inputs, t4, out, N, 7, 0.03125f, 451);
    }
    {   // f3: C=256, C4=64, PT=4
        dim3 grid((N + 4 - 1) / 4, B);
        gather_level<64, 4, 6, false><<<grid, 256>>>(inputs, t3, out, N, 14, 0.0625f, 195);
    }
    {   // f2: C=128, C4=32, PT=8
        dim3 grid((N + 8 - 1) / 8, B);
        gather_level<32, 8, 5, false><<<grid, 256>>>(inputs, t2, out, N, 28, 0.125f, 67);
    }
    {   // f1: C=64, C4=16, PT=16  (+ coord channels 0..2)
        dim3 grid((N + 16 - 1) / 16, B);
        gather_level<16, 16, 4, true><<<grid, 256>>>(inputs, t1, out, N, 56, 0.25f, 3);
    }
}

// round 9
// speedup vs baseline: 3.6451x; 1.0413x over previous
#include <cuda_runtime.h>
#include <cstdint>

// Shapes (fixed): B=4, N=50000
//  f1:[B,64,56,56] f2:[B,128,28,28] f3:[B,256,14,14] f4:[B,512,7,7]
//  out:[B,N,963] = 3 coord + 64 + 128 + 256 + 512

#define BMAX 4

// Transposed feature scratch: [b][x][y][c] (channel-contiguous per texel)
__device__ float g_t1[BMAX * 56 * 56 * 64];
__device__ float g_t2[BMAX * 28 * 28 * 128];
__device__ float g_t3[BMAX * 14 * 14 * 256];
__device__ float g_t4[BMAX * 7  * 7  * 512];

// ---------------------------------------------------------------------------
// Fused transpose: all four [B,C,S,S] -> [B,S,S,C] in one launch.
// Range boundaries are exact multiples of 256 (B=4), so each 256-thread block
// handles exactly one tensor: no intra-block divergence.
// ---------------------------------------------------------------------------
__device__ __forceinline__ void tr_body(const float* __restrict__ in,
                                        float* __restrict__ out,
                                        int C, int S, int idx) {
    int c = idx % C;
    int y = (idx / C) % S;
    int x = (idx / (C * S)) % S;
    int b = idx / (C * S * S);
    out[idx] = in[((b * C + c) * S + x) * S + y];
}

__global__ __launch_bounds__(256)
void transpose_all(const float* __restrict__ f1, const float* __restrict__ f2,
                   const float* __restrict__ f3, const float* __restrict__ f4,
                   float* __restrict__ t1, float* __restrict__ t2,
                   float* __restrict__ t3, float* __restrict__ t4,
                   int n1, int n2, int n3, int n4) {
    int idx = blockIdx.x * blockDim.x + threadIdx.x;
    if (idx < n1)                     { tr_body(f1, t1, 64, 56, idx); return; }
    idx -= n1;
    if (idx < n2)                     { tr_body(f2, t2, 128, 28, idx); return; }
    idx -= n2;
    if (idx < n3)                     { tr_body(f3, t3, 256, 14, idx); return; }
    idx -= n3;
    if (idx < n4)                     { tr_body(f4, t4, 512, 7, idx); }
}

// ---------------------------------------------------------------------------
// Bilinear params for one level. Matches the reference exactly, including the
// all-zero-weight case when the clipped coord is an integer (floor==ceil).
__device__ __forceinline__ void level_params(float h, float w, float invsc,
                                             int S, int C, int base,
                                             float* wout, int* oout) {
    float x = fminf(h * invsc, (float)(S - 1));
    float y = fminf(w * invsc, (float)(S - 1));
    float x1f = floorf(x), x2f = ceilf(x);
    float y1f = floorf(y), y2f = ceilf(y);
    int x1 = (int)x1f, x2 = (int)x2f, y1 = (int)y1f, y2 = (int)y2f;
    float ax2 = x2f - x, ax1 = x - x1f;
    float ay2 = y2f - y, ay1 = y - y1f;
    oout[0] = base + (x1 * S + y1) * C;   // Q11
    oout[1] = base + (x2 * S + y1) * C;   // Q21
    oout[2] = base + (x1 * S + y2) * C;   // Q12
    oout[3] = base + (x2 * S + y2) * C;   // Q22
    wout[0] = ax2 * ay2;
    wout[1] = ax1 * ay2;
    wout[2] = ax2 * ay1;
    wout[3] = ax1 * ay1;
}

// ---------------------------------------------------------------------------
// One level's gather body. Block = 256 threads = PT points x C4 float4-chans.
// float4 corner loads; streaming scalar stores (963-stride rows are only
// 4B-aligned). Same-level/same-batch blocks are adjacent in blockIdx.x so
// concurrent CTAs share one batch's slice of one level in L1/L2.
// ---------------------------------------------------------------------------
template<int C4, int PT, int LOG_C4, bool WRITE_COORD>
__device__ __forceinline__ void gather_body(int lbid,
                                            const float* __restrict__ coord,
                                            const float* __restrict__ t,
                                            float* __restrict__ out,
                                            int N, int S, float invsc, int ch_off) {
    __shared__ float sw[PT][4];
    __shared__ int   so[PT][4];

    const int bpb = (N + PT - 1) / PT;      // blocks per batch at this level
    const int b   = lbid / bpb;
    const int n0  = (lbid - b * bpb) * PT;
    const int tid = threadIdx.x;
    constexpr int C = C4 * 4;

    if (tid < PT) {
        int n = n0 + tid;
        if (n < N) {
            float X = coord[3 * n + 0];
            float Y = coord[3 * n + 1];
            float Z = coord[3 * n + 2];
            float negZ = -Z;
            float h = fminf(fmaxf(250.0f * (-Y) / negZ + 112.0f, 0.0f), 223.0f);
            float w = fminf(fmaxf(250.0f * X / negZ + 112.0f, 0.0f), 223.0f);
            level_params(h, w, invsc, S, C, b * S * S * C, sw[tid], so[tid]);
            if (WRITE_COORD) {
                float* oc = out + ((size_t)b * N + n) * 963;
                __stcs(oc + 0, X);
                __stcs(oc + 1, Y);
                __stcs(oc + 2, Z);
            }
        }
    }
    __syncthreads();

    const int p = tid >> LOG_C4;
    const int c = (tid & (C4 - 1)) * 4;
    const int n = n0 + p;
    if (n >= N) return;

    const float w0 = sw[p][0], w1 = sw[p][1], w2 = sw[p][2], w3 = sw[p][3];
    const float4 q0 = *(const float4*)(t + so[p][0] + c);
    const float4 q1 = *(const float4*)(t + so[p][1] + c);
    const float4 q2 = *(const float4*)(t + so[p][2] + c);
    const float4 q3 = *(const float4*)(t + so[p][3] + c);

    float* o = out + ((size_t)b * N + n) * 963 + ch_off + c;
    __stcs(o + 0, w0 * q0.x + w1 * q1.x + w2 * q2.x + w3 * q3.x);
    __stcs(o + 1, w0 * q0.y + w1 * q1.y + w2 * q2.y + w3 * q3.y);
    __stcs(o + 2, w0 * q0.z + w1 * q1.z + w2 * q2.z + w3 * q3.z);
    __stcs(o + 3, w0 * q0.w + w1 * q1.w + w2 * q2.w + w3 * q3.w);
}

// ---------------------------------------------------------------------------
// Fused gather: one launch, levels partitioned over blockIdx.x (f4 first).
// e4/e3/e2 are the cumulative block-range ends for levels 4,3,2.
// ---------------------------------------------------------------------------
__global__ __launch_bounds__(256)
void gather_all(const float* __restrict__ coord,
                const float* __restrict__ t1, const float* __restrict__ t2,
                const float* __restrict__ t3, const float* __restrict__ t4,
                float* __restrict__ out, int N,
                int e4, int e3, int e2) {
    int bid = blockIdx.x;
    if (bid < e4) {
        gather_body<128, 2, 7, false>(bid, coord, t4, out, N, 7, 0.03125f, 451);
    } else if (bid < e3) {
        gather_body<64, 4, 6, false>(bid - e4, coord, t3, out, N, 14, 0.0625f, 195);
    } else if (bid < e2) {
        gather_body<32, 8, 5, false>(bid - e3, coord, t2, out, N, 28, 0.125f, 67);
    } else {
        gather_body<16, 16, 4, true>(bid - e2, coord, t1, out, N, 56, 0.25f, 3);
    }
}

// ---------------------------------------------------------------------------
extern "C" void kernel_launch(void* const* d_in, const int* in_sizes, int n_in,
                              void* d_out, int out_size) {
    const float* inputs = (const float*)d_in[0];  // [B,N,3]; coord = inputs[0]
    const float* f1 = (const float*)d_in[1];
    const float* f2 = (const float*)d_in[2];
    const float* f3 = (const float*)d_in[3];
    const float* f4 = (const float*)d_in[4];
    float* out = (float*)d_out;

    const int B = in_sizes[1] / (64 * 56 * 56);
    const int N = in_sizes[0] / (3 * B);

    float* t1; float* t2; float* t3; float* t4;
    cudaGetSymbolAddress((void**)&t1, g_t1);
    cudaGetSymbolAddress((void**)&t2, g_t2);
    cudaGetSymbolAddress((void**)&t3, g_t3);
    cudaGetSymbolAddress((void**)&t4, g_t4);

    const int n1 = B * 64 * 56 * 56;
    const int n2 = B * 128 * 28 * 28;
    const int n3 = B * 256 * 14 * 14;
    const int n4 = B * 512 * 7 * 7;
    {
        int total = n1 + n2 + n3 + n4;
        transpose_all<<<(total + 255) / 256, 256>>>(f1, f2, f3, f4,
                                                    t1, t2, t3, t4,
                                                    n1, n2, n3, n4);
    }

    const int nb4 = ((N + 1) / 2)  * B;
    const int nb3 = ((N + 3) / 4)  * B;
    const int nb2 = ((N + 7) / 8)  * B;
    const int nb1 = ((N + 15) / 16) * B;
    const int e4 = nb4;
    const int e3 = e4 + nb3;
    const int e2 = e3 + nb2;
    const int total_blocks = e2 + nb1;

    gather_all<<<total_blocks, 256>>>(inputs, t1, t2, t3, t4, out, N, e4, e3, e2);
}

// round 11
// speedup vs baseline: 3.6745x; 1.0081x over previous
#include <cuda_runtime.h>
#include <cstdint>

// Shapes (fixed): B=4, N=50000
//  f1:[B,64,56,56] f2:[B,128,28,28] f3:[B,256,14,14] f4:[B,512,7,7]
//  out:[B,N,963] = 3 coord + 64 + 128 + 256 + 512

#define BMAX 4

// Transposed feature scratch: [b][x][y][c] (channel-contiguous per texel)
__device__ float g_t1[BMAX * 56 * 56 * 64];
__device__ float g_t2[BMAX * 28 * 28 * 128];
__device__ float g_t3[BMAX * 14 * 14 * 256];
__device__ float g_t4[BMAX * 7  * 7  * 512];

// ---------------------------------------------------------------------------
// Fused transpose: all four [B,C,S,S] -> [B,S,S,C] in one launch.
// Range boundaries are exact multiples of 256 (B=4): no intra-block divergence.
// ---------------------------------------------------------------------------
__device__ __forceinline__ void tr_body(const float* __restrict__ in,
                                        float* __restrict__ out,
                                        int C, int S, int idx) {
    int c = idx % C;
    int y = (idx / C) % S;
    int x = (idx / (C * S)) % S;
    int b = idx / (C * S * S);
    out[idx] = in[((b * C + c) * S + x) * S + y];
}

__global__ __launch_bounds__(256)
void transpose_all(const float* __restrict__ f1, const float* __restrict__ f2,
                   const float* __restrict__ f3, const float* __restrict__ f4,
                   float* __restrict__ t1, float* __restrict__ t2,
                   float* __restrict__ t3, float* __restrict__ t4,
                   int n1, int n2, int n3, int n4) {
    int idx = blockIdx.x * blockDim.x + threadIdx.x;
    if (idx < n1)                     { tr_body(f1, t1, 64, 56, idx); return; }
    idx -= n1;
    if (idx < n2)                     { tr_body(f2, t2, 128, 28, idx); return; }
    idx -= n2;
    if (idx < n3)                     { tr_body(f3, t3, 256, 14, idx); return; }
    idx -= n3;
    if (idx < n4)                     { tr_body(f4, t4, 512, 7, idx); }
}

// ---------------------------------------------------------------------------
// Bilinear params for one level. Matches the reference exactly, including the
// all-zero-weight case when the clipped coord is an integer (floor==ceil).
__device__ __forceinline__ void level_params(float h, float w, float invsc,
                                             int S, int C, int base,
                                             float* wout, int* oout) {
    float x = fminf(h * invsc, (float)(S - 1));
    float y = fminf(w * invsc, (float)(S - 1));
    float x1f = floorf(x), x2f = ceilf(x);
    float y1f = floorf(y), y2f = ceilf(y);
    int x1 = (int)x1f, x2 = (int)x2f, y1 = (int)y1f, y2 = (int)y2f;
    float ax2 = x2f - x, ax1 = x - x1f;
    float ay2 = y2f - y, ay1 = y - y1f;
    oout[0] = base + (x1 * S + y1) * C;   // Q11
    oout[1] = base + (x2 * S + y1) * C;   // Q21
    oout[2] = base + (x1 * S + y2) * C;   // Q12
    oout[3] = base + (x2 * S + y2) * C;   // Q22
    wout[0] = ax2 * ay2;
    wout[1] = ax1 * ay2;
    wout[2] = ax2 * ay1;
    wout[3] = ax1 * ay1;
}

// ---------------------------------------------------------------------------
// One level's gather body. Block = 256 threads = PT points x TPP threads.
// Each thread owns 4 channels spaced TPP apart (q, q+TPP, q+2TPP, q+3TPP):
//  - every STG.32 has lane-consecutive addresses -> 1 dense wavefront
//  - every LDG.32 is lane-consecutive 128B -> 1 dense wavefront
//  - all 16 loads share 4 base addresses; TPP*j offsets are immediates.
// Streaming stores keep the 770MB write stream out of L2.
// ---------------------------------------------------------------------------
template<int TPP, int PT, int LOG_TPP, bool WRITE_COORD>
__device__ __forceinline__ void gather_body(int lbid,
                                            const float* __restrict__ coord,
                                            const float* __restrict__ t,
                                            float* __restrict__ out,
                                            int N, int S, float invsc, int ch_off) {
    __shared__ float sw[PT][4];
    __shared__ int   so[PT][4];

    const int bpb = (N + PT - 1) / PT;      // blocks per batch at this level
    const int b   = lbid / bpb;
    const int n0  = (lbid - b * bpb) * PT;
    const int tid = threadIdx.x;
    constexpr int C = TPP * 4;

    if (tid < PT) {
        int n = n0 + tid;
        if (n < N) {
            float X = coord[3 * n + 0];
            float Y = coord[3 * n + 1];
            float Z = coord[3 * n + 2];
            float negZ = -Z;
            float h = fminf(fmaxf(250.0f * (-Y) / negZ + 112.0f, 0.0f), 223.0f);
            float w = fminf(fmaxf(250.0f * X / negZ + 112.0f, 0.0f), 223.0f);
            level_params(h, w, invsc, S, C, b * S * S * C, sw[tid], so[tid]);
            if (WRITE_COORD) {
                float* oc = out + ((size_t)b * N + n) * 963;
                __stcs(oc + 0, X);
                __stcs(oc + 1, Y);
                __stcs(oc + 2, Z);
            }
        }
    }
    __syncthreads();

    const int p = tid >> LOG_TPP;
    const int q = tid & (TPP - 1);
    const int n = n0 + p;
    if (n >= N) return;

    const float w0 = sw[p][0], w1 = sw[p][1], w2 = sw[p][2], w3 = sw[p][3];
    const float* __restrict__ b0 = t + so[p][0] + q;
    const float* __restrict__ b1 = t + so[p][1] + q;
    const float* __restrict__ b2 = t + so[p][2] + q;
    const float* __restrict__ b3 = t + so[p][3] + q;
    float* o = out + ((size_t)b * N + n) * 963 + ch_off + q;

    // Load all 16 corner values first (max MLP), then combine and store.
    float v0[4], v1[4], v2[4], v3[4];
    #pragma unroll
    for (int j = 0; j < 4; j++) {
        v0[j] = b0[TPP * j];
        v1[j] = b1[TPP * j];
        v2[j] = b2[TPP * j];
        v3[j] = b3[TPP * j];
    }
    #pragma unroll
    for (int j = 0; j < 4; j++) {
        __stcs(o + TPP * j, w0 * v0[j] + w1 * v1[j] + w2 * v2[j] + w3 * v3[j]);
    }
}

// ---------------------------------------------------------------------------
// Fused gather: one launch, levels partitioned over blockIdx.x (f4 first).
// ---------------------------------------------------------------------------
__global__ __launch_bounds__(256)
void gather_all(const float* __restrict__ coord,
                const float* __restrict__ t1, const float* __restrict__ t2,
                const float* __restrict__ t3, const float* __restrict__ t4,
                float* __restrict__ out, int N,
                int e4, int e3, int e2) {
    int bid = blockIdx.x;
    if (bid < e4) {
        gather_body<128, 2, 7, false>(bid, coord, t4, out, N, 7, 0.03125f, 451);
    } else if (bid < e3) {
        gather_body<64, 4, 6, false>(bid - e4, coord, t3, out, N, 14, 0.0625f, 195);
    } else if (bid < e2) {
        gather_body<32, 8, 5, false>(bid - e3, coord, t2, out, N, 28, 0.125f, 67);
    } else {
        gather_body<16, 16, 4, true>(bid - e2, coord, t1, out, N, 56, 0.25f, 3);
    }
}

// ---------------------------------------------------------------------------
extern "C" void kernel_launch(void* const* d_in, const int* in_sizes, int n_in,
                              void* d_out, int out_size) {
    const float* inputs = (const float*)d_in[0];  // [B,N,3]; coord = inputs[0]
    const float* f1 = (const float*)d_in[1];
    const float* f2 = (const float*)d_in[2];
    const float* f3 = (const float*)d_in[3];
    const float* f4 = (const float*)d_in[4];
    float* out = (float*)d_out;

    const int B = in_sizes[1] / (64 * 56 * 56);
    const int N = in_sizes[0] / (3 * B);

    float* t1; float* t2; float* t3; float* t4;
    cudaGetSymbolAddress((void**)&t1, g_t1);
    cudaGetSymbolAddress((void**)&t2, g_t2);
    cudaGetSymbolAddress((void**)&t3, g_t3);
    cudaGetSymbolAddress((void**)&t4, g_t4);

    const int n1 = B * 64 * 56 * 56;
    const int n2 = B * 128 * 28 * 28;
    const int n3 = B * 256 * 14 * 14;
    const int n4 = B * 512 * 7 * 7;
    {
        int total = n1 + n2 + n3 + n4;
        transpose_all<<<(total + 255) / 256, 256>>>(f1, f2, f3, f4,
                                                    t1, t2, t3, t4,
                                                    n1, n2, n3, n4);
    }

    const int nb4 = ((N + 1) / 2)  * B;
    const int nb3 = ((N + 3) / 4)  * B;
    const int nb2 = ((N + 7) / 8)  * B;
    const int nb1 = ((N + 15) / 16) * B;
    const int e4 = nb4;
    const int e3 = e4 + nb3;
    const int e2 = e3 + nb2;
    const int total_blocks = e2 + nb1;

    gather_all<<<total_blocks, 256>>>(inputs, t1, t2, t3, t4, out, N, e4, e3, e2);
}

// round 13
// speedup vs baseline: 4.2268x; 1.1503x over previous
#include <cuda_runtime.h>
#include <cstdint>

// Shapes (fixed): B=4, N=50000
//  f1:[B,64,56,56] f2:[B,128,28,28] f3:[B,256,14,14] f4:[B,512,7,7]
//  out:[B,N,963] = 3 coord + 64 + 128 + 256 + 512

#define BMAX 4

// Transposed feature scratch: [b][x][y][c] (channel-contiguous per texel)
__device__ float g_t1[BMAX * 56 * 56 * 64];
__device__ float g_t2[BMAX * 28 * 28 * 128];
__device__ float g_t3[BMAX * 14 * 14 * 256];
__device__ float g_t4[BMAX * 7  * 7  * 512];

// ---------------------------------------------------------------------------
// Fused transpose: all four [B,C,S,S] -> [B,S,S,C] in one launch.
// ---------------------------------------------------------------------------
__device__ __forceinline__ void tr_body(const float* __restrict__ in,
                                        float* __restrict__ out,
                                        int C, int S, int idx) {
    int c = idx % C;
    int y = (idx / C) % S;
    int x = (idx / (C * S)) % S;
    int b = idx / (C * S * S);
    out[idx] = in[((b * C + c) * S + x) * S + y];
}

__global__ __launch_bounds__(256)
void transpose_all(const float* __restrict__ f1, const float* __restrict__ f2,
                   const float* __restrict__ f3, const float* __restrict__ f4,
                   float* __restrict__ t1, float* __restrict__ t2,
                   float* __restrict__ t3, float* __restrict__ t4,
                   int n1, int n2, int n3, int n4) {
    int idx = blockIdx.x * blockDim.x + threadIdx.x;
    if (idx < n1)                     { tr_body(f1, t1, 64, 56, idx); return; }
    idx -= n1;
    if (idx < n2)                     { tr_body(f2, t2, 128, 28, idx); return; }
    idx -= n2;
    if (idx < n3)                     { tr_body(f3, t3, 256, 14, idx); return; }
    idx -= n3;
    if (idx < n4)                     { tr_body(f4, t4, 512, 7, idx); }
}

// ---------------------------------------------------------------------------
// Bilinear params for one level. Matches the reference exactly, including the
// all-zero-weight case when the clipped coord is an integer (floor==ceil).
// ---------------------------------------------------------------------------
__device__ __forceinline__ void level_params(float h, float w, float invsc,
                                             int S, int C, int base,
                                             float4* wout, int4* oout) {
    float x = fminf(h * invsc, (float)(S - 1));
    float y = fminf(w * invsc, (float)(S - 1));
    float x1f = floorf(x), x2f = ceilf(x);
    float y1f = floorf(y), y2f = ceilf(y);
    int x1 = (int)x1f, x2 = (int)x2f, y1 = (int)y1f, y2 = (int)y2f;
    float ax2 = x2f - x, ax1 = x - x1f;
    float ay2 = y2f - y, ay1 = y - y1f;
    *oout = make_int4(base + (x1 * S + y1) * C,    // Q11
                      base + (x2 * S + y1) * C,    // Q21
                      base + (x1 * S + y2) * C,    // Q12
                      base + (x2 * S + y2) * C);   // Q22
    *wout = make_float4(ax2 * ay2, ax1 * ay2, ax2 * ay1, ax1 * ay1);
}

// ---------------------------------------------------------------------------
// One level's gather body. Block = 256 threads = PT points x TPP threads.
// Each thread owns 4 channels spaced TPP apart -> dense (1-wavefront) LDG.32
// and STG.32. Params packed as float4/int4 -> 2x LDS.128 per thread.
// tile index and batch come straight from the 2D grid: no integer division.
// Streaming stores keep the 770MB write stream out of L2.
// ---------------------------------------------------------------------------
template<int TPP, int PT, int LOG_TPP, bool WRITE_COORD>
__device__ __forceinline__ void gather_body(int tile, int b,
                                            const float* __restrict__ coord,
                                            const float* __restrict__ t,
                                            float* __restrict__ out,
                                            int N, int S, float invsc, int ch_off) {
    __shared__ float4 sw[PT];
    __shared__ int4   so[PT];

    const int n0  = tile * PT;
    const int tid = threadIdx.x;
    constexpr int C = TPP * 4;

    if (tid < PT) {
        int n = n0 + tid;
        if (n < N) {
            float X = coord[3 * n + 0];
            float Y = coord[3 * n + 1];
            float Z = coord[3 * n + 2];
            float negZ = -Z;
            float h = fminf(fmaxf(250.0f * (-Y) / negZ + 112.0f, 0.0f), 223.0f);
            float w = fminf(fmaxf(250.0f * X / negZ + 112.0f, 0.0f), 223.0f);
            level_params(h, w, invsc, S, C, b * S * S * C, &sw[tid], &so[tid]);
            if (WRITE_COORD) {
                float* oc = out + ((unsigned)(b * N + n)) * 963u;
                __stcs(oc + 0, X);
                __stcs(oc + 1, Y);
                __stcs(oc + 2, Z);
            }
        }
    }
    __syncthreads();

    const int p = tid >> LOG_TPP;
    const int q = tid & (TPP - 1);
    const int n = n0 + p;
    if (n >= N) return;

    const float4 w4 = sw[p];
    const int4   o4 = so[p];
    const float* __restrict__ b0 = t + o4.x + q;
    const float* __restrict__ b1 = t + o4.y + q;
    const float* __restrict__ b2 = t + o4.z + q;
    const float* __restrict__ b3 = t + o4.w + q;
    float* o = out + ((unsigned)(b * N + n) * 963u + (unsigned)(ch_off + q));

    // Load all 16 corner values first (max MLP), then combine and store.
    float v0[4], v1[4], v2[4], v3[4];
    #pragma unroll
    for (int j = 0; j < 4; j++) {
        v0[j] = b0[TPP * j];
        v1[j] = b1[TPP * j];
        v2[j] = b2[TPP * j];
        v3[j] = b3[TPP * j];
    }
    #pragma unroll
    for (int j = 0; j < 4; j++) {
        __stcs(o + TPP * j, w4.x * v0[j] + w4.y * v1[j] + w4.z * v2[j] + w4.w * v3[j]);
    }
}

// ---------------------------------------------------------------------------
// Fused gather: blockIdx.y = batch; blockIdx.x partitioned by level (f4 first).
// e4/e3/e2 are cumulative per-batch block-range ends for levels 4,3,2.
// ---------------------------------------------------------------------------
__global__ __launch_bounds__(256)
void gather_all(const float* __restrict__ coord,
                const float* __restrict__ t1, const float* __restrict__ t2,
                const float* __restrict__ t3, const float* __restrict__ t4,
                float* __restrict__ out, int N,
                int e4, int e3, int e2) {
    const int bid = blockIdx.x;
    const int b   = blockIdx.y;
    if (bid < e4) {
        gather_body<128, 2, 7, false>(bid, b, coord, t4, out, N, 7, 0.03125f, 451);
    } else if (bid < e3) {
        gather_body<64, 4, 6, false>(bid - e4, b, coord, t3, out, N, 14, 0.0625f, 195);
    } else if (bid < e2) {
        gather_body<32, 8, 5, false>(bid - e3, b, coord, t2, out, N, 28, 0.125f, 67);
    } else {
        gather_body<16, 16, 4, true>(bid - e2, b, coord, t1, out, N, 56, 0.25f, 3);
    }
}

// ---------------------------------------------------------------------------
extern "C" void kernel_launch(void* const* d_in, const int* in_sizes, int n_in,
                              void* d_out, int out_size) {
    const float* inputs = (const float*)d_in[0];  // [B,N,3]; coord = inputs[0]
    const float* f1 = (const float*)d_in[1];
    const float* f2 = (const float*)d_in[2];
    const float* f3 = (const float*)d_in[3];
    const float* f4 = (const float*)d_in[4];
    float* out = (float*)d_out;

    const int B = in_sizes[1] / (64 * 56 * 56);
    const int N = in_sizes[0] / (3 * B);

    float* t1; float* t2; float* t3; float* t4;
    cudaGetSymbolAddress((void**)&t1, g_t1);
    cudaGetSymbolAddress((void**)&t2, g_t2);
    cudaGetSymbolAddress((void**)&t3, g_t3);
    cudaGetSymbolAddress((void**)&t4, g_t4);

    const int n1 = B * 64 * 56 * 56;
    const int n2 = B * 128 * 28 * 28;
    const int n3 = B * 256 * 14 * 14;
    const int n4 = B * 512 * 7 * 7;
    {
        int total = n1 + n2 + n3 + n4;
        transpose_all<<<(total + 255) / 256, 256>>>(f1, f2, f3, f4,
                                                    t1, t2, t3, t4,
                                                    n1, n2, n3, n4);
    }

    // Per-batch block counts per level (N divides each PT for N=50000).
    const int nb4 = (N + 1) / 2;
    const int nb3 = (N + 3) / 4;
    const int nb2 = (N + 7) / 8;
    const int nb1 = (N + 15) / 16;
    const int e4 = nb4;
    const int e3 = e4 + nb3;
    const int e2 = e3 + nb2;
    const int xblocks = e2 + nb1;

    dim3 grid(xblocks, B);
    gather_all<<<grid, 256>>>(inputs, t1, t2, t3, t4, out, N, e4, e3, e2);
}